// round 6
// baseline (speedup 1.0000x reference)
#include <cuda_runtime.h>
#include <cstdint>

#define Hh 2048
#define Ww 2048
#define NPIX (Hh*Ww)            // 4194304
#define BIGL NPIX               // background label
#define NLBL (NPIX+1)
#define KTOP 16
#define NBLK_TOP 120
#define MINSZ 64

// ---------------- device scratch (no allocations allowed) ----------------
__device__ int   g_labA[NPIX];
__device__ int   g_labB[NPIX];
__device__ int   g_counts[NLBL];
__device__ unsigned long long g_cand[NBLK_TOP*KTOP];
__device__ int   g_lids[KTOP];
__device__ int   g_cnts[KTOP];
__device__ int   g_bbox[KTOP][4];              // y0,y1,x0,x1
__device__ int   g_cls[KTOP];
__device__ float g_roi[KTOP*227*227];
__device__ float g_h1[KTOP*16*56*56];
__device__ float g_h2[KTOP*32*27*27];

// ---------------- f32x2 helpers ----------------
__device__ __forceinline__ unsigned long long pack2(float v){
    unsigned long long r; asm("mov.b64 %0, {%1, %1};" : "=l"(r) : "f"(v)); return r;
}
__device__ __forceinline__ void fma2(unsigned long long& a, unsigned long long v, unsigned long long w){
    asm("fma.rn.f32x2 %0, %1, %2, %0;" : "+l"(a) : "l"(v), "l"(w));
}
__device__ __forceinline__ float2 unpack2(unsigned long long a){
    float2 f; asm("mov.b64 {%0, %1}, %2;" : "=f"(f.x), "=f"(f.y) : "l"(a)); return f;
}

// ================= fused conv1+conv2+conv3+threshold =================
// block (8,32) = 256 threads -> 32x32 output tile, 4 consecutive x px / thread.
// Two passes over oc (16 oc each) so accumulators = 32 u64 -> 2 blocks/SM.
#define CF_SF   0
#define CF_SW2  9792
#define CF_SX   10944
#define CF_SW1  12276
#define CF_SW3  12564
#define CF_TOTAL (12596*4)
#define FSTR 1224   // 34*36

__global__ __launch_bounds__(256, 2) void k_conv123(const float* __restrict__ x,
                                                    const float* __restrict__ w1,
                                                    const float* __restrict__ w2,
                                                    const float* __restrict__ w3){
    extern __shared__ float sm[];
    float* sF  = sm + CF_SF;
    float* sW2 = sm + CF_SW2;
    float* sX  = sm + CF_SX;
    float* sW1 = sm + CF_SW1;
    float* sW3 = sm + CF_SW3;

    int tx = threadIdx.x;           // 0..7
    int ty = threadIdx.y;           // 0..31
    int tid = ty*8 + tx;

    for (int i = tid; i < 288; i += 256){
        int tap = i >> 5, oc = i & 31;
        sW1[i] = w1[oc*9 + tap];                      // [tap][oc]
    }
    if (tid < 32) sW3[tid] = w3[tid];

    int bx0 = blockIdx.x*32, by0 = blockIdx.y*32;

    // input tile 36x36, origin (by0-2, bx0-2), stride 37
    for (int i = tid; i < 36*36; i += 256){
        int yy = i/36, xxv = i%36;
        int gy = by0-2+yy, gx = bx0-2+xxv;
        float v = 0.f;
        if ((unsigned)gy < 2048u && (unsigned)gx < 2048u) v = x[(gy<<11)+gx];
        sX[yy*37 + xxv] = v;
    }

    float z0 = 0.f, z1 = 0.f, z2 = 0.f, z3 = 0.f;
    const unsigned long long* w1u = (const unsigned long long*)sW1;

    for (int p = 0; p < 2; p++){
        unsigned long long acc0[8], acc1[8], acc2[8], acc3[8];
        #pragma unroll
        for (int q = 0; q < 8; q++){ acc0[q]=0ull; acc1[q]=0ull; acc2[q]=0ull; acc3[q]=0ull; }

        for (int g = 0; g < 4; g++){
            __syncthreads();
            // weights for (pass p, group g): [icl][tap][16 oc]
            for (int i = tid; i < 1152; i += 256){
                int icl = i >> 7, r = i & 127, tap = r >> 4, ocl = r & 15;
                sW2[i] = w2[((size_t)(p*16+ocl)*32 + (g*8+icl))*9 + tap];
            }
            // conv1 for channels g*8 .. g*8+7 over 34x34 region
            for (int i = tid; i < 34*34; i += 256){
                int fy = i/34, fx = i - fy*34;
                const float* base = sX + fy*37 + fx;
                unsigned long long vp[9];
                #pragma unroll
                for (int r = 0; r < 3; r++)
                    #pragma unroll
                    for (int c = 0; c < 3; c++) vp[r*3+c] = pack2(base[r*37+c]);
                float* outp = sF + fy*36 + fx;
                #pragma unroll
                for (int q = 0; q < 4; q++){
                    unsigned long long a = 0ull;
                    #pragma unroll
                    for (int t = 0; t < 9; t++) fma2(a, vp[t], w1u[t*16 + g*4 + q]);
                    float2 f = unpack2(a);
                    outp[(2*q  )*FSTR] = fmaxf(f.x, 0.f);
                    outp[(2*q+1)*FSTR] = fmaxf(f.y, 0.f);
                }
            }
            __syncthreads();

            // conv2 accumulate: 4 px, 16 oc (8 u64), 8 ic
            const float* bp0 = sF + ty*36 + 4*tx;
            for (int icl = 0; icl < 8; icl++){
                const float* bp = bp0 + icl*FSTR;
                #pragma unroll
                for (int r = 0; r < 3; r++){
                    const float* rp = bp + r*36;
                    float4 A = *(const float4*)(rp);
                    float4 B = *(const float4*)(rp + 4);
                    unsigned long long pk[6];
                    pk[0] = pack2(A.x); pk[1] = pack2(A.y); pk[2] = pack2(A.z);
                    pk[3] = pack2(A.w); pk[4] = pack2(B.x); pk[5] = pack2(B.y);
                    const unsigned long long* wr = (const unsigned long long*)(sW2 + (icl*9 + r*3)*16);
                    #pragma unroll
                    for (int c = 0; c < 3; c++){
                        const unsigned long long* w = wr + c*8;
                        #pragma unroll
                        for (int q = 0; q < 8; q++){
                            unsigned long long wq = w[q];
                            fma2(acc0[q], pk[c+0], wq);
                            fma2(acc1[q], pk[c+1], wq);
                            fma2(acc2[q], pk[c+2], wq);
                            fma2(acc3[q], pk[c+3], wq);
                        }
                    }
                }
            }
        }
        // fold this oc-half into z in oc order (left-to-right fp32 sum preserved)
        #pragma unroll
        for (int q = 0; q < 8; q++){
            float wlo = sW3[p*16 + 2*q], whi = sW3[p*16 + 2*q + 1];
            float2 f;
            f = unpack2(acc0[q]); z0 += fmaxf(f.x,0.f)*wlo; z0 += fmaxf(f.y,0.f)*whi;
            f = unpack2(acc1[q]); z1 += fmaxf(f.x,0.f)*wlo; z1 += fmaxf(f.y,0.f)*whi;
            f = unpack2(acc2[q]); z2 += fmaxf(f.x,0.f)*wlo; z2 += fmaxf(f.y,0.f)*whi;
            f = unpack2(acc3[q]); z3 += fmaxf(f.x,0.f)*wlo; z3 += fmaxf(f.y,0.f)*whi;
        }
    }

    int y = by0 + ty, xg = bx0 + 4*tx;
    int ppix = (y<<11) + xg;
    int4 lab;
    lab.x = (z0 > 0.f) ? (ppix  ) : BIGL;
    lab.y = (z1 > 0.f) ? (ppix+1) : BIGL;
    lab.z = (z2 > 0.f) ? (ppix+2) : BIGL;
    lab.w = (z3 > 0.f) ? (ppix+3) : BIGL;
    *(int4*)(g_labA + ppix) = lab;
}

// ================= connected components: 8 exact Jacobi steps, 2x2-int4 blocks =================
// interior 64x64, region 80x80 valid at rows 1..80, cols 4..83 of an 82x88 tile; ring = BIGL.
// Step s only needs cells in [s, 79-s]^2 (region coords); out-of-window cells are never read inward.
#define CC_STRIDE 88
#define CC_CELLS  (82*CC_STRIDE)     // 7216
#define CC_SMEM   (2*CC_CELLS*4)     // 57728 B

__device__ __forceinline__ int4 cc_step4(int4 c, int4 u, int4 d, int l, int r){
    int4 o; int m;
    m = min(min(u.x,d.x), min(l,   c.y)); o.x = (c.x==BIGL) ? BIGL : min(c.x, m);
    m = min(min(u.y,d.y), min(c.x, c.z)); o.y = (c.y==BIGL) ? BIGL : min(c.y, m);
    m = min(min(u.z,d.z), min(c.y, c.w)); o.z = (c.z==BIGL) ? BIGL : min(c.z, m);
    m = min(min(u.w,d.w), min(c.z, r  )); o.w = (c.w==BIGL) ? BIGL : min(c.w, m);
    return o;
}

__global__ __launch_bounds__(1024) void k_cc(const int* __restrict__ src, int* __restrict__ dst){
    extern __shared__ int sh[];
    int* A = sh;
    int* B = sh + CC_CELLS;
    int tid = threadIdx.x;
    int gx0 = blockIdx.x*64 - 8, gy0 = blockIdx.y*64 - 8;

    // fill both buffers with BIGL (sentinels persist; valid cells overwritten / garbage-safe)
    for (int s = tid; s < CC_CELLS; s += 1024){ A[s] = BIGL; B[s] = BIGL; }
    __syncthreads();

    // load 80x80 valid region into A (int4 fast path)
    for (int v = tid; v < 1600; v += 1024){
        int vy = v/20, vx = (v%20)*4;
        int gy = gy0 + vy, gxb = gx0 + vx;
        int off = (1+vy)*CC_STRIDE + 4 + vx;
        if ((unsigned)gy < 2048u && gxb >= 0 && gxb + 3 < 2048){
            *(int4*)(A + off) = *(const int4*)(src + (gy<<11) + gxb);
        } else if ((unsigned)gy < 2048u){
            #pragma unroll
            for (int k = 0; k < 4; k++){
                int gx = gxb + k;
                A[off+k] = ((unsigned)gx < 2048u) ? src[(gy<<11)+gx] : BIGL;
            }
        }
    }
    __syncthreads();

    // 2x2-int4 block per thread: rows 2br,2br+1 ; x-cols 8bc..8bc+7  (400 active threads)
    int br = tid/10, bc = tid - br*10;
    bool act = tid < 400;
    int R0 = 2*br, R1 = R0 + 1, X0 = 8*bc;
    int off0 = (1+R0)*CC_STRIDE + 4 + X0;
    int off1 = off0 + CC_STRIDE;

    int* cur = A; int* nxt = B;
    #pragma unroll
    for (int s = 1; s <= 8; s++){
        if (act && R1 >= s && R0 <= 79-s && X0+7 >= s && X0 <= 79-s){
            int4 u0 = *(const int4*)(cur + off0 - CC_STRIDE);
            int4 u1 = *(const int4*)(cur + off0 - CC_STRIDE + 4);
            int4 c0 = *(const int4*)(cur + off0);
            int4 c1 = *(const int4*)(cur + off0 + 4);
            int4 e0 = *(const int4*)(cur + off1);
            int4 e1 = *(const int4*)(cur + off1 + 4);
            int4 d0 = *(const int4*)(cur + off1 + CC_STRIDE);
            int4 d1 = *(const int4*)(cur + off1 + CC_STRIDE + 4);
            int l0 = cur[off0-1], r0 = cur[off0+8];
            int l1 = cur[off1-1], r1 = cur[off1+8];
            *(int4*)(nxt + off0    ) = cc_step4(c0, u0, e0, l0,   c1.x);
            *(int4*)(nxt + off0 + 4) = cc_step4(c1, u1, e1, c0.w, r0  );
            *(int4*)(nxt + off1    ) = cc_step4(e0, c0, d0, l1,   e1.x);
            *(int4*)(nxt + off1 + 4) = cc_step4(e1, c1, d1, e0.w, r1  );
        }
        __syncthreads();
        int* t = cur; cur = nxt; nxt = t;
    }

    // write interior 64x64 (region cell (8,8) -> smem (9,12))
    int row = tid >> 4, c16 = tid & 15;
    int soff = (9 + row)*CC_STRIDE + 12 + c16*4;
    int gy = blockIdx.y*64 + row, gx = blockIdx.x*64 + c16*4;
    *(int4*)(dst + (gy<<11) + gx) = *(const int4*)(cur + soff);
}

// ---------------- histogram ----------------
__global__ void k_zero_counts(int off){
    int i = off + blockIdx.x*1024 + threadIdx.x;
    if (i < NLBL) g_counts[i] = 0;
}
__global__ void k_count(){
    int p = blockIdx.x*256 + threadIdx.x;
    int l = g_labA[p];
    unsigned mk = __match_any_sync(0xffffffffu, l);
    int leader = __ffs(mk) - 1;
    if ((threadIdx.x & 31) == leader && l != BIGL)
        atomicAdd(&g_counts[l], __popc(mk));
}

// ---------------- exact top-16 (count desc, label asc): two-stage ----------------
__global__ void k_topA(){
    __shared__ unsigned long long s[256*16];
    int chunk = (NLBL + NBLK_TOP - 1)/NBLK_TOP;
    int lo = blockIdx.x*chunk;
    int hi = min(NLBL, lo + chunk);
    unsigned long long best[16];
    #pragma unroll
    for (int i = 0; i < 16; i++) best[i] = 0ull;
    unsigned long long bmin = 0ull; int bpos = 0;
    for (int i = lo + threadIdx.x; i < hi; i += 256){
        unsigned long long key = ((unsigned long long)(unsigned)g_counts[i] << 32)
                               | (unsigned)(~(unsigned)i);
        if (key > bmin){
            best[bpos] = key;
            bmin = best[0]; bpos = 0;
            #pragma unroll
            for (int j = 1; j < 16; j++) if (best[j] < bmin){ bmin = best[j]; bpos = j; }
        }
    }
    for (int j = 0; j < 16; j++) s[threadIdx.x*16 + j] = best[j];
    __syncthreads();
    if (threadIdx.x < 32){
        for (int r = 0; r < 16; r++){
            unsigned long long m = 0ull; int mp = -1;
            for (int i = threadIdx.x; i < 4096; i += 32){
                unsigned long long v = s[i];
                if (v > m){ m = v; mp = i; }
            }
            for (int off = 16; off; off >>= 1){
                unsigned long long om = __shfl_down_sync(0xffffffffu, m, off);
                int op = __shfl_down_sync(0xffffffffu, mp, off);
                if (om > m){ m = om; mp = op; }
            }
            m  = __shfl_sync(0xffffffffu, m, 0);
            mp = __shfl_sync(0xffffffffu, mp, 0);
            if (threadIdx.x == 0){
                g_cand[blockIdx.x*16 + r] = m;
                if (mp >= 0) s[mp] = 0ull;
            }
            __syncwarp();
        }
    }
}
__global__ void k_topB(){
    __shared__ unsigned long long s[2048];
    int tid = threadIdx.x;
    for (int i = tid; i < 2048; i += 256) s[i] = (i < NBLK_TOP*16) ? g_cand[i] : 0ull;
    __syncthreads();
    if (tid < 32){
        for (int r = 0; r < 16; r++){
            unsigned long long m = 0ull; int mp = -1;
            for (int i = tid; i < 2048; i += 32){
                unsigned long long v = s[i];
                if (v > m){ m = v; mp = i; }
            }
            for (int off = 16; off; off >>= 1){
                unsigned long long om = __shfl_down_sync(0xffffffffu, m, off);
                int op = __shfl_down_sync(0xffffffffu, mp, off);
                if (om > m){ m = om; mp = op; }
            }
            m  = __shfl_sync(0xffffffffu, m, 0);
            mp = __shfl_sync(0xffffffffu, mp, 0);
            if (tid == 0){
                g_cnts[r] = (int)(m >> 32);
                g_lids[r] = (int)(~(unsigned)(m & 0xffffffffull));
                if (mp >= 0) s[mp] = 0ull;
            }
            __syncwarp();
        }
    }
}

// ---------------- bounding boxes ----------------
__global__ void k_bbinit(){
    int k = threadIdx.x;
    if (k < 16){ g_bbox[k][0] = 0x7FFFFFFF; g_bbox[k][1] = -1; g_bbox[k][2] = 0x7FFFFFFF; g_bbox[k][3] = -1; }
}
__global__ void k_bbox(){
    __shared__ int slid[16];
    __shared__ int sbb[16][4];
    int tid = threadIdx.x;
    if (tid < 16){
        slid[tid] = g_lids[tid];
        sbb[tid][0] = 0x7FFFFFFF; sbb[tid][1] = -1; sbb[tid][2] = 0x7FFFFFFF; sbb[tid][3] = -1;
    }
    __syncthreads();
    int base = blockIdx.x*1024;
    for (int q = 0; q < 4; q++){
        int p = base + q*256 + tid;
        int l = g_labA[p];
        if (l != BIGL){
            int y = p >> 11, x = p & 2047;
            #pragma unroll
            for (int k = 0; k < 16; k++) if (l == slid[k]){
                if (y < sbb[k][0]) atomicMin(&sbb[k][0], y);
                if (y > sbb[k][1]) atomicMax(&sbb[k][1], y);
                if (x < sbb[k][2]) atomicMin(&sbb[k][2], x);
                if (x > sbb[k][3]) atomicMax(&sbb[k][3], x);
            }
        }
    }
    __syncthreads();
    if (tid < 16 && sbb[tid][0] != 0x7FFFFFFF){
        atomicMin(&g_bbox[tid][0], sbb[tid][0]);
        atomicMax(&g_bbox[tid][1], sbb[tid][1]);
        atomicMin(&g_bbox[tid][2], sbb[tid][2]);
        atomicMax(&g_bbox[tid][3], sbb[tid][3]);
    }
}

// ---------------- ROI bilinear resize (227x227) ----------------
__global__ void k_roi(const float* __restrict__ img){
    int k = blockIdx.x;
    int y0 = g_bbox[k][0], y1 = g_bbox[k][1], x0 = g_bbox[k][2], x1 = g_bbox[k][3];
    if (y0 == 0x7FFFFFFF){ y0 = 0; y1 = 2047; x0 = 0; x1 = 2047; }  // empty comp: argmax(all-false)=0
    float dy = (float)(y1 - y0), dx = (float)(x1 - x0);
    for (int idx = threadIdx.x; idx < 227*227; idx += blockDim.x){
        int i = idx/227, j = idx%227;
        float gy = (float)y0 + ((float)i/226.0f)*dy;
        float gx = (float)x0 + ((float)j/226.0f)*dx;
        int yf = min(max((int)floorf(gy), 0), 2046);
        int xf = min(max((int)floorf(gx), 0), 2046);
        float fy = gy - (float)yf, fx = gx - (float)xf;
        const float* r0 = img + (yf<<11) + xf;
        float v00 = r0[0], v01 = r0[1], v10 = r0[2048], v11 = r0[2049];
        g_roi[k*51529 + idx] = (1.f-fy)*((1.f-fx)*v00 + fx*v01) + fy*((1.f-fx)*v10 + fx*v11);
    }
}

// ---------------- classifier conv1: 7x7 s4 VALID, 1->16, relu ----------------
__global__ void k_c1(const float* __restrict__ cw1){
    __shared__ float sw[784];
    int tid = threadIdx.x;
    for (int i = tid; i < 784; i += 256) sw[i] = cw1[i];
    __syncthreads();
    int o = blockIdx.x*256 + tid;           // 16*16*56*56 = 802816 total
    int k = o/50176, r = o%50176, oc = r/3136, s = r%3136, oy = s/56, ox = s%56;
    const float* roi = g_roi + k*51529;
    const float* wb = sw + oc*49;
    float a = 0.f;
    #pragma unroll
    for (int ky = 0; ky < 7; ky++){
        const float* rr = roi + (oy*4+ky)*227 + ox*4;
        #pragma unroll
        for (int kx = 0; kx < 7; kx++) a += rr[kx]*wb[ky*7+kx];
    }
    g_h1[o] = fmaxf(a, 0.f);
}

// ---------------- classifier conv2: 3x3 s2 VALID, 16->32, relu ----------------
__global__ void k_c2(const float* __restrict__ cw2){
    __shared__ float sw[4608];
    int tid = threadIdx.x;
    for (int i = tid; i < 4608; i += 256) sw[i] = cw2[i];
    __syncthreads();
    int o = blockIdx.x*256 + tid;           // 16*32*27*27 = 373248
    int k = o/23328, r = o%23328, oc = r/729, s = r%729, oy = s/27, ox = s%27;
    const float* h = g_h1 + (size_t)k*16*3136;
    float a = 0.f;
    for (int ic = 0; ic < 16; ic++){
        const float* hb = h + ic*3136 + (oy*2)*56 + ox*2;
        const float* wb = sw + (oc*16+ic)*9;
        #pragma unroll
        for (int ky = 0; ky < 3; ky++)
            #pragma unroll
            for (int kx = 0; kx < 3; kx++)
                a += hb[ky*56+kx]*wb[ky*3+kx];
    }
    g_h2[o] = fmaxf(a, 0.f);
}

// ---------------- global mean + fc + argmax ----------------
__global__ void k_cls(const float* __restrict__ fc){
    __shared__ float ssum[32];
    int k = blockIdx.x;
    int tid = threadIdx.x, w = tid >> 5, lane = tid & 31;
    for (int oc = w*4; oc < w*4+4; oc++){
        float s = 0.f;
        const float* h = g_h2 + ((size_t)(k*32+oc))*729;
        for (int i = lane; i < 729; i += 32) s += h[i];
        for (int off = 16; off; off >>= 1) s += __shfl_down_sync(0xffffffffu, s, off);
        if (lane == 0) ssum[oc] = s;
    }
    __syncthreads();
    if (tid == 0){
        float best = -1e30f; int bc = 0;
        for (int c = 0; c < 4; c++){
            float lg = 0.f;
            for (int oc = 0; oc < 32; oc++) lg += (ssum[oc]*(1.0f/729.0f))*fc[oc*4+c];
            if (lg > best){ best = lg; bc = c; }
        }
        g_cls[k] = bc;
    }
}

// ---------------- final mask composition (vectorized) ----------------
__global__ void k_final(float* __restrict__ out){
    __shared__ int slid[16], scls[16];
    int tid = threadIdx.x;
    if (tid < 16){
        slid[tid] = (g_cnts[tid] >= MINSZ) ? g_lids[tid] : -1;   // -1 never matches a label
        scls[tid] = g_cls[tid];
    }
    __syncthreads();
    int p4 = (blockIdx.x*256 + tid)*4;
    int4 l = *(const int4*)(g_labA + p4);
    int ls0 = l.x, ls1 = l.y, ls2 = l.z, ls3 = l.w;
    int c0 = -1, c1 = -1, c2 = -1, c3 = -1;
    #pragma unroll
    for (int k = 0; k < 16; k++){
        int lid = slid[k], cc = scls[k];
        if (ls0 == lid) c0 = cc;
        if (ls1 == lid) c1 = cc;
        if (ls2 == lid) c2 = cc;
        if (ls3 == lid) c3 = cc;
    }
    #pragma unroll
    for (int ch = 0; ch < 4; ch++){
        float4 o;
        o.x = (c0 == ch) ? 1.f : 0.f;
        o.y = (c1 == ch) ? 1.f : 0.f;
        o.z = (c2 == ch) ? 1.f : 0.f;
        o.w = (c3 == ch) ? 1.f : 0.f;
        *(float4*)(out + (size_t)ch*NPIX + p4) = o;
    }
}

// ---------------- launch ----------------
extern "C" void kernel_launch(void* const* d_in, const int* in_sizes, int n_in,
                              void* d_out, int out_size){
    const float *x = nullptr, *w1 = nullptr, *w2 = nullptr, *w3 = nullptr;
    const float *cw1 = nullptr, *cw2 = nullptr, *fc = nullptr;
    for (int i = 0; i < n_in; i++){
        switch (in_sizes[i]){
            case 4194304: x   = (const float*)d_in[i]; break;
            case 288:     w1  = (const float*)d_in[i]; break;
            case 9216:    w2  = (const float*)d_in[i]; break;
            case 32:      w3  = (const float*)d_in[i]; break;
            case 784:     cw1 = (const float*)d_in[i]; break;
            case 4608:    cw2 = (const float*)d_in[i]; break;
            case 128:     fc  = (const float*)d_in[i]; break;
            default: break;
        }
    }
    float* out = (float*)d_out;

    cudaFuncSetAttribute(k_conv123, cudaFuncAttributeMaxDynamicSharedMemorySize, CF_TOTAL);
    cudaFuncSetAttribute(k_cc, cudaFuncAttributeMaxDynamicSharedMemorySize, CC_SMEM);

    // launches 1-5: independent setup, placed first so ncu (-s 5 -c 1) captures k_conv123
    k_zero_counts<<<1025, 1024>>>(0);
    k_zero_counts<<<1025, 1024>>>(1049600);
    k_zero_counts<<<1025, 1024>>>(2099200);
    k_zero_counts<<<1025, 1024>>>(3148800);
    k_bbinit<<<1, 16>>>();

    // launch 6: the big one
    k_conv123<<<dim3(64,64), dim3(8,32), CF_TOTAL>>>(x, w1, w2, w3);

    int* la = nullptr; int* lb = nullptr;
    cudaGetSymbolAddress((void**)&la, g_labA);
    cudaGetSymbolAddress((void**)&lb, g_labB);
    for (int i = 0; i < 4; i++){
        k_cc<<<dim3(32,32), 1024, CC_SMEM>>>(la, lb);   // A -> B
        k_cc<<<dim3(32,32), 1024, CC_SMEM>>>(lb, la);   // B -> A
    }

    k_count<<<NPIX/256, 256>>>();
    k_topA<<<NBLK_TOP, 256>>>();
    k_topB<<<1, 256>>>();

    k_bbox<<<NPIX/1024, 256>>>();

    k_roi<<<16, 256>>>(x);
    k_c1<<<802816/256, 256>>>(cw1);
    k_c2<<<373248/256, 256>>>(cw2);
    k_cls<<<16, 256>>>(fc);

    k_final<<<NPIX/1024, 256>>>(out);
}

// round 7
// speedup vs baseline: 1.1558x; 1.1558x over previous
#include <cuda_runtime.h>
#include <cstdint>

#define Hh 2048
#define Ww 2048
#define NPIX (Hh*Ww)            // 4194304
#define BIGL NPIX               // background label
#define NLBL (NPIX+1)
#define KTOP 16
#define NBLK_TOP 120
#define MINSZ 64

// ---------------- device scratch (no allocations allowed) ----------------
__device__ int   g_labA[NPIX];
__device__ int   g_labB[NPIX];
__device__ int   g_counts[NLBL];
__device__ unsigned long long g_cand[NBLK_TOP*KTOP];
__device__ int   g_lids[KTOP];
__device__ int   g_cnts[KTOP];
__device__ int   g_bbox[KTOP][4];              // y0,y1,x0,x1
__device__ int   g_cls[KTOP];
__device__ float g_roi[KTOP*227*227];
__device__ float g_h1[KTOP*16*56*56];
__device__ float g_h2[KTOP*32*27*27];

// ---------------- f32x2 helpers ----------------
__device__ __forceinline__ unsigned long long pack2(float v){
    unsigned long long r; asm("mov.b64 %0, {%1, %1};" : "=l"(r) : "f"(v)); return r;
}
__device__ __forceinline__ void fma2(unsigned long long& a, unsigned long long v, unsigned long long w){
    asm("fma.rn.f32x2 %0, %1, %2, %0;" : "+l"(a) : "l"(v), "l"(w));
}
__device__ __forceinline__ float2 unpack2(unsigned long long a){
    float2 f; asm("mov.b64 {%0, %1}, %2;" : "=f"(f.x), "=f"(f.y) : "l"(a)); return f;
}

// ================= fused conv1+conv2+conv3+threshold =================
// block (8,32) = 256 threads -> 32x32 output tile, 4 consecutive x px / thread.
// Two passes over oc (16 oc each) so accumulators = 32 u64 -> 2 blocks/SM.
#define CF_SF   0
#define CF_SW2  9792
#define CF_SX   10944
#define CF_SW1  12276
#define CF_SW3  12564
#define CF_TOTAL (12596*4)
#define FSTR 1224   // 34*36

__global__ __launch_bounds__(256, 2) void k_conv123(const float* __restrict__ x,
                                                    const float* __restrict__ w1,
                                                    const float* __restrict__ w2,
                                                    const float* __restrict__ w3){
    extern __shared__ float sm[];
    float* sF  = sm + CF_SF;
    float* sW2 = sm + CF_SW2;
    float* sX  = sm + CF_SX;
    float* sW1 = sm + CF_SW1;
    float* sW3 = sm + CF_SW3;

    int tx = threadIdx.x;           // 0..7
    int ty = threadIdx.y;           // 0..31
    int tid = ty*8 + tx;

    for (int i = tid; i < 288; i += 256){
        int tap = i >> 5, oc = i & 31;
        sW1[i] = w1[oc*9 + tap];                      // [tap][oc]
    }
    if (tid < 32) sW3[tid] = w3[tid];

    int bx0 = blockIdx.x*32, by0 = blockIdx.y*32;

    // input tile 36x36, origin (by0-2, bx0-2), stride 37
    for (int i = tid; i < 36*36; i += 256){
        int yy = i/36, xxv = i%36;
        int gy = by0-2+yy, gx = bx0-2+xxv;
        float v = 0.f;
        if ((unsigned)gy < 2048u && (unsigned)gx < 2048u) v = x[(gy<<11)+gx];
        sX[yy*37 + xxv] = v;
    }

    float z0 = 0.f, z1 = 0.f, z2 = 0.f, z3 = 0.f;
    const unsigned long long* w1u = (const unsigned long long*)sW1;

    for (int p = 0; p < 2; p++){
        unsigned long long acc0[8], acc1[8], acc2[8], acc3[8];
        #pragma unroll
        for (int q = 0; q < 8; q++){ acc0[q]=0ull; acc1[q]=0ull; acc2[q]=0ull; acc3[q]=0ull; }

        for (int g = 0; g < 4; g++){
            __syncthreads();
            // weights for (pass p, group g): [icl][tap][16 oc]
            for (int i = tid; i < 1152; i += 256){
                int icl = i >> 7, r = i & 127, tap = r >> 4, ocl = r & 15;
                sW2[i] = w2[((size_t)(p*16+ocl)*32 + (g*8+icl))*9 + tap];
            }
            // conv1 for channels g*8 .. g*8+7 over 34x34 region
            for (int i = tid; i < 34*34; i += 256){
                int fy = i/34, fx = i - fy*34;
                const float* base = sX + fy*37 + fx;
                unsigned long long vp[9];
                #pragma unroll
                for (int r = 0; r < 3; r++)
                    #pragma unroll
                    for (int c = 0; c < 3; c++) vp[r*3+c] = pack2(base[r*37+c]);
                float* outp = sF + fy*36 + fx;
                #pragma unroll
                for (int q = 0; q < 4; q++){
                    unsigned long long a = 0ull;
                    #pragma unroll
                    for (int t = 0; t < 9; t++) fma2(a, vp[t], w1u[t*16 + g*4 + q]);
                    float2 f = unpack2(a);
                    outp[(2*q  )*FSTR] = fmaxf(f.x, 0.f);
                    outp[(2*q+1)*FSTR] = fmaxf(f.y, 0.f);
                }
            }
            __syncthreads();

            // conv2 accumulate: 4 px, 16 oc (8 u64), 8 ic
            const float* bp0 = sF + ty*36 + 4*tx;
            for (int icl = 0; icl < 8; icl++){
                const float* bp = bp0 + icl*FSTR;
                #pragma unroll
                for (int r = 0; r < 3; r++){
                    const float* rp = bp + r*36;
                    float4 A = *(const float4*)(rp);
                    float4 B = *(const float4*)(rp + 4);
                    unsigned long long pk[6];
                    pk[0] = pack2(A.x); pk[1] = pack2(A.y); pk[2] = pack2(A.z);
                    pk[3] = pack2(A.w); pk[4] = pack2(B.x); pk[5] = pack2(B.y);
                    const unsigned long long* wr = (const unsigned long long*)(sW2 + (icl*9 + r*3)*16);
                    #pragma unroll
                    for (int c = 0; c < 3; c++){
                        const unsigned long long* w = wr + c*8;
                        #pragma unroll
                        for (int q = 0; q < 8; q++){
                            unsigned long long wq = w[q];
                            fma2(acc0[q], pk[c+0], wq);
                            fma2(acc1[q], pk[c+1], wq);
                            fma2(acc2[q], pk[c+2], wq);
                            fma2(acc3[q], pk[c+3], wq);
                        }
                    }
                }
            }
        }
        // fold this oc-half into z in oc order (left-to-right fp32 sum preserved)
        #pragma unroll
        for (int q = 0; q < 8; q++){
            float wlo = sW3[p*16 + 2*q], whi = sW3[p*16 + 2*q + 1];
            float2 f;
            f = unpack2(acc0[q]); z0 += fmaxf(f.x,0.f)*wlo; z0 += fmaxf(f.y,0.f)*whi;
            f = unpack2(acc1[q]); z1 += fmaxf(f.x,0.f)*wlo; z1 += fmaxf(f.y,0.f)*whi;
            f = unpack2(acc2[q]); z2 += fmaxf(f.x,0.f)*wlo; z2 += fmaxf(f.y,0.f)*whi;
            f = unpack2(acc3[q]); z3 += fmaxf(f.x,0.f)*wlo; z3 += fmaxf(f.y,0.f)*whi;
        }
    }

    int y = by0 + ty, xg = bx0 + 4*tx;
    int ppix = (y<<11) + xg;
    int4 lab;
    lab.x = (z0 > 0.f) ? (ppix  ) : BIGL;
    lab.y = (z1 > 0.f) ? (ppix+1) : BIGL;
    lab.z = (z2 > 0.f) ? (ppix+2) : BIGL;
    lab.w = (z3 > 0.f) ? (ppix+3) : BIGL;
    *(int4*)(g_labA + ppix) = lab;
}

// ================= connected components: 8 exact Jacobi steps, int4, sentinel ring =================
// interior 64x64, region 80x80 valid at rows 1..80, cols 4..83 of an 82x88 tile; ring = BIGL.
// Step s only needs cells in [s, 79-s]^2 (region coords). Early-exit when a full step changes
// nothing (min-propagation is monotone; future windows are subsets -> all later steps identity).
#define CC_STRIDE 88
#define CC_CELLS  (82*CC_STRIDE)     // 7216
#define CC_SMEM   (2*CC_CELLS*4)     // 57728 B

__device__ __forceinline__ int cc_step(const int* __restrict__ cur, int* __restrict__ nxt, int off){
    int4 c = *(const int4*)(cur + off);
    int4 u = *(const int4*)(cur + off - CC_STRIDE);
    int4 d = *(const int4*)(cur + off + CC_STRIDE);
    int l = cur[off-1], r = cur[off+4];
    int4 o; int m;
    m = min(min(u.x,d.x), min(l,   c.y)); o.x = (c.x==BIGL) ? BIGL : min(c.x, m);
    m = min(min(u.y,d.y), min(c.x, c.z)); o.y = (c.y==BIGL) ? BIGL : min(c.y, m);
    m = min(min(u.z,d.z), min(c.y, c.w)); o.z = (c.z==BIGL) ? BIGL : min(c.z, m);
    m = min(min(u.w,d.w), min(c.z, r  )); o.w = (c.w==BIGL) ? BIGL : min(c.w, m);
    *(int4*)(nxt + off) = o;
    return (o.x^c.x) | (o.y^c.y) | (o.z^c.z) | (o.w^c.w);
}

__global__ __launch_bounds__(1024) void k_cc(const int* __restrict__ src, int* __restrict__ dst){
    extern __shared__ int sh[];
    int* A = sh;
    int* B = sh + CC_CELLS;
    int tid = threadIdx.x;
    int gx0 = blockIdx.x*64 - 8, gy0 = blockIdx.y*64 - 8;

    // fill both buffers with BIGL (sentinels persist; valid cells overwritten)
    for (int s = tid; s < CC_CELLS; s += 1024){ A[s] = BIGL; B[s] = BIGL; }
    __syncthreads();

    // load 80x80 valid region into A (int4 fast path)
    for (int v = tid; v < 1600; v += 1024){
        int vy = v/20, vx = (v%20)*4;
        int gy = gy0 + vy, gxb = gx0 + vx;
        int off = (1+vy)*CC_STRIDE + 4 + vx;
        if ((unsigned)gy < 2048u && gxb >= 0 && gxb + 3 < 2048){
            *(int4*)(A + off) = *(const int4*)(src + (gy<<11) + gxb);
        } else if ((unsigned)gy < 2048u){
            #pragma unroll
            for (int k = 0; k < 4; k++){
                int gx = gxb + k;
                A[off+k] = ((unsigned)gx < 2048u) ? src[(gy<<11)+gx] : BIGL;
            }
        }
    }
    __syncthreads();

    // this thread's two cells (region coords)
    int j0 = tid;
    int vy0 = j0/20, cx0 = (j0 - vy0*20)*4;
    int off0 = (1 + vy0)*CC_STRIDE + 4 + cx0;
    int j1 = tid + 1024;
    int vy1 = j1/20, cx1 = (j1 - vy1*20)*4;
    int off1 = (1 + vy1)*CC_STRIDE + 4 + cx1;
    bool has1 = (j1 < 1600);

    int* cur = A; int* nxt = B;
    for (int s = 1; s <= 8; s++){
        int changed = 0;
        if (vy0 >= s && vy0 <= 79-s && cx0+3 >= s && cx0 <= 79-s) changed |= cc_step(cur, nxt, off0);
        if (has1 && vy1 >= s && vy1 <= 79-s && cx1+3 >= s && cx1 <= 79-s) changed |= cc_step(cur, nxt, off1);
        if (!__syncthreads_or(changed)) break;   // stationary -> remaining steps are identity
        int* t = cur; cur = nxt; nxt = t;
    }

    // write interior 64x64 (region cell (8,8) -> smem (9,12))
    int row = tid >> 4, c16 = tid & 15;
    int soff = (9 + row)*CC_STRIDE + 12 + c16*4;
    int gy = blockIdx.y*64 + row, gx = blockIdx.x*64 + c16*4;
    *(int4*)(dst + (gy<<11) + gx) = *(const int4*)(cur + soff);
}

// ---------------- histogram ----------------
__global__ void k_zero_counts(){
    int i = blockIdx.x*1024 + threadIdx.x;
    if (i < NLBL) g_counts[i] = 0;
}
__global__ void k_count(){
    int p4 = (blockIdx.x*256 + threadIdx.x)*4;
    int4 l = *(const int4*)(g_labA + p4);
    #pragma unroll
    for (int k = 0; k < 4; k++){
        int lab = (k==0) ? l.x : (k==1) ? l.y : (k==2) ? l.z : l.w;
        unsigned mk = __match_any_sync(0xffffffffu, lab);
        int leader = __ffs(mk) - 1;
        if ((threadIdx.x & 31) == leader && lab != BIGL)
            atomicAdd(&g_counts[lab], __popc(mk));
    }
}

// ---------------- exact top-16 (count desc, label asc): two-stage ----------------
__global__ void k_topA(){
    __shared__ unsigned long long s[256*16];
    int chunk = (NLBL + NBLK_TOP - 1)/NBLK_TOP;
    int lo = blockIdx.x*chunk;
    int hi = min(NLBL, lo + chunk);
    unsigned long long best[16];
    #pragma unroll
    for (int i = 0; i < 16; i++) best[i] = 0ull;
    unsigned long long bmin = 0ull; int bpos = 0;
    for (int i = lo + threadIdx.x; i < hi; i += 256){
        unsigned long long key = ((unsigned long long)(unsigned)g_counts[i] << 32)
                               | (unsigned)(~(unsigned)i);
        if (key > bmin){
            best[bpos] = key;
            bmin = best[0]; bpos = 0;
            #pragma unroll
            for (int j = 1; j < 16; j++) if (best[j] < bmin){ bmin = best[j]; bpos = j; }
        }
    }
    for (int j = 0; j < 16; j++) s[threadIdx.x*16 + j] = best[j];
    __syncthreads();
    if (threadIdx.x < 32){
        for (int r = 0; r < 16; r++){
            unsigned long long m = 0ull; int mp = -1;
            for (int i = threadIdx.x; i < 4096; i += 32){
                unsigned long long v = s[i];
                if (v > m){ m = v; mp = i; }
            }
            for (int off = 16; off; off >>= 1){
                unsigned long long om = __shfl_down_sync(0xffffffffu, m, off);
                int op = __shfl_down_sync(0xffffffffu, mp, off);
                if (om > m){ m = om; mp = op; }
            }
            m  = __shfl_sync(0xffffffffu, m, 0);
            mp = __shfl_sync(0xffffffffu, mp, 0);
            if (threadIdx.x == 0){
                g_cand[blockIdx.x*16 + r] = m;
                if (mp >= 0) s[mp] = 0ull;
            }
            __syncwarp();
        }
    }
}
__global__ void k_topB(){
    __shared__ unsigned long long s[2048];
    int tid = threadIdx.x;
    for (int i = tid; i < 2048; i += 256) s[i] = (i < NBLK_TOP*16) ? g_cand[i] : 0ull;
    __syncthreads();
    if (tid < 32){
        for (int r = 0; r < 16; r++){
            unsigned long long m = 0ull; int mp = -1;
            for (int i = tid; i < 2048; i += 32){
                unsigned long long v = s[i];
                if (v > m){ m = v; mp = i; }
            }
            for (int off = 16; off; off >>= 1){
                unsigned long long om = __shfl_down_sync(0xffffffffu, m, off);
                int op = __shfl_down_sync(0xffffffffu, mp, off);
                if (om > m){ m = om; mp = op; }
            }
            m  = __shfl_sync(0xffffffffu, m, 0);
            mp = __shfl_sync(0xffffffffu, mp, 0);
            if (tid == 0){
                g_cnts[r] = (int)(m >> 32);
                g_lids[r] = (int)(~(unsigned)(m & 0xffffffffull));
                if (mp >= 0) s[mp] = 0ull;
            }
            __syncwarp();
        }
    }
}

// ---------------- bounding boxes ----------------
__global__ void k_bbinit(){
    int k = threadIdx.x;
    if (k < 16){ g_bbox[k][0] = 0x7FFFFFFF; g_bbox[k][1] = -1; g_bbox[k][2] = 0x7FFFFFFF; g_bbox[k][3] = -1; }
}
__global__ void k_bbox(){
    __shared__ int slid[16];
    __shared__ int sbb[16][4];
    int tid = threadIdx.x;
    if (tid < 16){
        slid[tid] = g_lids[tid];
        sbb[tid][0] = 0x7FFFFFFF; sbb[tid][1] = -1; sbb[tid][2] = 0x7FFFFFFF; sbb[tid][3] = -1;
    }
    __syncthreads();
    int base = blockIdx.x*1024;
    for (int q = 0; q < 4; q++){
        int p = base + q*256 + tid;
        int l = g_labA[p];
        if (l != BIGL){
            int y = p >> 11, x = p & 2047;
            #pragma unroll
            for (int k = 0; k < 16; k++) if (l == slid[k]){
                if (y < sbb[k][0]) atomicMin(&sbb[k][0], y);
                if (y > sbb[k][1]) atomicMax(&sbb[k][1], y);
                if (x < sbb[k][2]) atomicMin(&sbb[k][2], x);
                if (x > sbb[k][3]) atomicMax(&sbb[k][3], x);
            }
        }
    }
    __syncthreads();
    if (tid < 16 && sbb[tid][0] != 0x7FFFFFFF){
        atomicMin(&g_bbox[tid][0], sbb[tid][0]);
        atomicMax(&g_bbox[tid][1], sbb[tid][1]);
        atomicMin(&g_bbox[tid][2], sbb[tid][2]);
        atomicMax(&g_bbox[tid][3], sbb[tid][3]);
    }
}

// ---------------- ROI bilinear resize (227x227) ----------------
__global__ void k_roi(const float* __restrict__ img){
    int k = blockIdx.x;
    int y0 = g_bbox[k][0], y1 = g_bbox[k][1], x0 = g_bbox[k][2], x1 = g_bbox[k][3];
    if (y0 == 0x7FFFFFFF){ y0 = 0; y1 = 2047; x0 = 0; x1 = 2047; }  // empty comp: argmax(all-false)=0
    float dy = (float)(y1 - y0), dx = (float)(x1 - x0);
    for (int idx = threadIdx.x; idx < 227*227; idx += blockDim.x){
        int i = idx/227, j = idx%227;
        float gy = (float)y0 + ((float)i/226.0f)*dy;
        float gx = (float)x0 + ((float)j/226.0f)*dx;
        int yf = min(max((int)floorf(gy), 0), 2046);
        int xf = min(max((int)floorf(gx), 0), 2046);
        float fy = gy - (float)yf, fx = gx - (float)xf;
        const float* r0 = img + (yf<<11) + xf;
        float v00 = r0[0], v01 = r0[1], v10 = r0[2048], v11 = r0[2049];
        g_roi[k*51529 + idx] = (1.f-fy)*((1.f-fx)*v00 + fx*v01) + fy*((1.f-fx)*v10 + fx*v11);
    }
}

// ---------------- classifier conv1: 7x7 s4 VALID, 1->16, relu ----------------
__global__ void k_c1(const float* __restrict__ cw1){
    __shared__ float sw[784];
    int tid = threadIdx.x;
    for (int i = tid; i < 784; i += 256) sw[i] = cw1[i];
    __syncthreads();
    int o = blockIdx.x*256 + tid;           // 16*16*56*56 = 802816 total
    int k = o/50176, r = o%50176, oc = r/3136, s = r%3136, oy = s/56, ox = s%56;
    const float* roi = g_roi + k*51529;
    const float* wb = sw + oc*49;
    float a = 0.f;
    #pragma unroll
    for (int ky = 0; ky < 7; ky++){
        const float* rr = roi + (oy*4+ky)*227 + ox*4;
        #pragma unroll
        for (int kx = 0; kx < 7; kx++) a += rr[kx]*wb[ky*7+kx];
    }
    g_h1[o] = fmaxf(a, 0.f);
}

// ---------------- classifier conv2: 3x3 s2 VALID, 16->32, relu ----------------
__global__ void k_c2(const float* __restrict__ cw2){
    __shared__ float sw[4608];
    int tid = threadIdx.x;
    for (int i = tid; i < 4608; i += 256) sw[i] = cw2[i];
    __syncthreads();
    int o = blockIdx.x*256 + tid;           // 16*32*27*27 = 373248
    int k = o/23328, r = o%23328, oc = r/729, s = r%729, oy = s/27, ox = s%27;
    const float* h = g_h1 + (size_t)k*16*3136;
    float a = 0.f;
    for (int ic = 0; ic < 16; ic++){
        const float* hb = h + ic*3136 + (oy*2)*56 + ox*2;
        const float* wb = sw + (oc*16+ic)*9;
        #pragma unroll
        for (int ky = 0; ky < 3; ky++)
            #pragma unroll
            for (int kx = 0; kx < 3; kx++)
                a += hb[ky*56+kx]*wb[ky*3+kx];
    }
    g_h2[o] = fmaxf(a, 0.f);
}

// ---------------- global mean + fc + argmax ----------------
__global__ void k_cls(const float* __restrict__ fc){
    __shared__ float ssum[32];
    int k = blockIdx.x;
    int tid = threadIdx.x, w = tid >> 5, lane = tid & 31;
    for (int oc = w*4; oc < w*4+4; oc++){
        float s = 0.f;
        const float* h = g_h2 + ((size_t)(k*32+oc))*729;
        for (int i = lane; i < 729; i += 32) s += h[i];
        for (int off = 16; off; off >>= 1) s += __shfl_down_sync(0xffffffffu, s, off);
        if (lane == 0) ssum[oc] = s;
    }
    __syncthreads();
    if (tid == 0){
        float best = -1e30f; int bc = 0;
        for (int c = 0; c < 4; c++){
            float lg = 0.f;
            for (int oc = 0; oc < 32; oc++) lg += (ssum[oc]*(1.0f/729.0f))*fc[oc*4+c];
            if (lg > best){ best = lg; bc = c; }
        }
        g_cls[k] = bc;
    }
}

// ---------------- final mask composition (vectorized) ----------------
__global__ void k_final(float* __restrict__ out){
    __shared__ int slid[16], scls[16];
    int tid = threadIdx.x;
    if (tid < 16){
        slid[tid] = (g_cnts[tid] >= MINSZ) ? g_lids[tid] : -1;   // -1 never matches a label
        scls[tid] = g_cls[tid];
    }
    __syncthreads();
    int p4 = (blockIdx.x*256 + tid)*4;
    int4 l = *(const int4*)(g_labA + p4);
    int c0 = -1, c1 = -1, c2 = -1, c3 = -1;
    #pragma unroll
    for (int k = 0; k < 16; k++){
        int lid = slid[k], cc = scls[k];
        if (l.x == lid) c0 = cc;
        if (l.y == lid) c1 = cc;
        if (l.z == lid) c2 = cc;
        if (l.w == lid) c3 = cc;
    }
    #pragma unroll
    for (int ch = 0; ch < 4; ch++){
        float4 o;
        o.x = (c0 == ch) ? 1.f : 0.f;
        o.y = (c1 == ch) ? 1.f : 0.f;
        o.z = (c2 == ch) ? 1.f : 0.f;
        o.w = (c3 == ch) ? 1.f : 0.f;
        *(float4*)(out + (size_t)ch*NPIX + p4) = o;
    }
}

// ---------------- launch ----------------
extern "C" void kernel_launch(void* const* d_in, const int* in_sizes, int n_in,
                              void* d_out, int out_size){
    const float *x = nullptr, *w1 = nullptr, *w2 = nullptr, *w3 = nullptr;
    const float *cw1 = nullptr, *cw2 = nullptr, *fc = nullptr;
    for (int i = 0; i < n_in; i++){
        switch (in_sizes[i]){
            case 4194304: x   = (const float*)d_in[i]; break;
            case 288:     w1  = (const float*)d_in[i]; break;
            case 9216:    w2  = (const float*)d_in[i]; break;
            case 32:      w3  = (const float*)d_in[i]; break;
            case 784:     cw1 = (const float*)d_in[i]; break;
            case 4608:    cw2 = (const float*)d_in[i]; break;
            case 128:     fc  = (const float*)d_in[i]; break;
            default: break;
        }
    }
    float* out = (float*)d_out;

    cudaFuncSetAttribute(k_conv123, cudaFuncAttributeMaxDynamicSharedMemorySize, CF_TOTAL);
    cudaFuncSetAttribute(k_cc, cudaFuncAttributeMaxDynamicSharedMemorySize, CC_SMEM);

    k_conv123<<<dim3(64,64), dim3(8,32), CF_TOTAL>>>(x, w1, w2, w3);

    int* la = nullptr; int* lb = nullptr;
    cudaGetSymbolAddress((void**)&la, g_labA);
    cudaGetSymbolAddress((void**)&lb, g_labB);
    for (int i = 0; i < 4; i++){
        k_cc<<<dim3(32,32), 1024, CC_SMEM>>>(la, lb);   // A -> B
        k_cc<<<dim3(32,32), 1024, CC_SMEM>>>(lb, la);   // B -> A
    }

    k_zero_counts<<<(NLBL+1023)/1024, 1024>>>();
    k_count<<<NPIX/1024, 256>>>();
    k_topA<<<NBLK_TOP, 256>>>();
    k_topB<<<1, 256>>>();

    k_bbinit<<<1, 16>>>();
    k_bbox<<<NPIX/1024, 256>>>();

    k_roi<<<16, 256>>>(x);
    k_c1<<<802816/256, 256>>>(cw1);
    k_c2<<<373248/256, 256>>>(cw2);
    k_cls<<<16, 256>>>(fc);

    k_final<<<NPIX/1024, 256>>>(out);
}

// round 9
// speedup vs baseline: 1.2016x; 1.0397x over previous
#include <cuda_runtime.h>
#include <cstdint>

#define Hh 2048
#define Ww 2048
#define NPIX (Hh*Ww)            // 4194304
#define BIGL NPIX               // background label
#define NLBL (NPIX+1)
#define KTOP 16
#define NBLK_TOP 120
#define MINSZ 64

// ---------------- device scratch (no allocations allowed) ----------------
__device__ int   g_labA[NPIX];
__device__ int   g_labB[NPIX];
__device__ int   g_counts[NLBL];
__device__ unsigned long long g_cand[NBLK_TOP*KTOP];
__device__ int   g_lids[KTOP];
__device__ int   g_cnts[KTOP];
__device__ int   g_bbox[KTOP][4];
__device__ int   g_cls[KTOP];
__device__ float g_roi[KTOP*227*227];
__device__ float g_h1[KTOP*16*56*56];
__device__ float g_h2[KTOP*32*27*27];

// ---------------- helpers ----------------
__device__ __forceinline__ unsigned long long pack2(float v){
    unsigned long long r; asm("mov.b64 %0, {%1, %1};" : "=l"(r) : "f"(v)); return r;
}
__device__ __forceinline__ void fma2(unsigned long long& a, unsigned long long v, unsigned long long w){
    asm("fma.rn.f32x2 %0, %1, %2, %0;" : "+l"(a) : "l"(v), "l"(w));
}
__device__ __forceinline__ float2 unpack2(unsigned long long a){
    float2 f; asm("mov.b64 {%0, %1}, %2;" : "=f"(f.x), "=f"(f.y) : "l"(a)); return f;
}
__device__ __forceinline__ unsigned f2tf(float v){
    unsigned u; asm("cvt.rna.tf32.f32 %0, %1;" : "=r"(u) : "f"(v)); return u;
}
__device__ __forceinline__ void mma8(float* d, unsigned a0, unsigned a1, unsigned a2, unsigned a3,
                                     unsigned b0, unsigned b1){
    asm volatile("mma.sync.aligned.m16n8k8.row.col.f32.tf32.tf32.f32 "
        "{%0,%1,%2,%3}, {%4,%5,%6,%7}, {%8,%9}, {%0,%1,%2,%3};"
        : "+f"(d[0]), "+f"(d[1]), "+f"(d[2]), "+f"(d[3])
        : "r"(a0), "r"(a1), "r"(a2), "r"(a3), "r"(b0), "r"(b1));
}

// ================= conv via mma.sync tf32 (3xTF32 fp32 emulation) =================
// 32x32 px tile, 256 threads (8 warps, each warp = 4 rows = 128 px = M).
// K = 288 (32ic x 9tap) as 4 ic-groups x 9 taps x k8; 3 split passes hi*hi, hi*lo, lo*hi.
// smem (floats):
//   sAhi [34][34][10]  11560     (k-cols: pair c <-> ic (2c,2c+1), ICP=10 pad)
//   sAlo               11560
//   sB   2 planes x [9t][4g][4nt][8n][4c] float2 = 9216 f2 = 18432 f
//   sX   [36][37]      1332
//   sW1  [9t][32oc]    288
//   sW3  32
#define ICP 10
#define OF_AHI 0
#define OF_ALO 11560
#define OF_B   23120
#define OF_X   41552
#define OF_W1  42884
#define OF_W3  43172
#define CONV_SMEM (43204*4)   // 172816 B

__global__ void __launch_bounds__(256) k_conv_tc(const float* __restrict__ x,
                                                 const float* __restrict__ w1,
                                                 const float* __restrict__ w2,
                                                 const float* __restrict__ w3){
    extern __shared__ float sm[];
    float*  sAhi = sm + OF_AHI;
    float*  sAlo = sm + OF_ALO;
    float2* sB   = (float2*)(sm + OF_B);
    float*  sX   = sm + OF_X;
    float*  sW1  = sm + OF_W1;
    float*  sW3  = sm + OF_W3;

    int tid = threadIdx.x;
    int wid = tid >> 5, lane = tid & 31;
    int lq = lane >> 2, lc = lane & 3;     // groupID, threadID-in-group

    for (int i = tid; i < 288; i += 256){
        int tap = i >> 5, oc = i & 31;
        sW1[i] = w1[oc*9 + tap];           // [tap][oc]
    }
    if (tid < 32) sW3[tid] = w3[tid];

    // B: fragment-ready, k-permuted (col c <-> ic 2c, col c+4 <-> ic 2c+1)
    for (int i = tid; i < 4608; i += 256){
        int c = i & 3, n = (i >> 2) & 7, nt = (i >> 5) & 3, g = (i >> 7) & 3, t = i >> 9;
        int oc = nt*8 + n, ic = g*8 + 2*c;
        float wa = w2[((size_t)oc*32 + ic)*9 + t];
        float wb = w2[((size_t)oc*32 + ic + 1)*9 + t];
        unsigned ha = f2tf(wa), hb = f2tf(wb);
        float la = wa - __uint_as_float(ha), lb = wb - __uint_as_float(hb);
        sB[i]        = make_float2(__uint_as_float(ha), __uint_as_float(hb));
        sB[4608 + i] = make_float2(__uint_as_float(f2tf(la)), __uint_as_float(f2tf(lb)));
    }

    int bx0 = blockIdx.x*32, by0 = blockIdx.y*32;
    // x tile 36x36 (stride 37), origin (by0-2, bx0-2), zero-padded
    for (int i = tid; i < 1296; i += 256){
        int r = i/36, cxx = i - r*36;
        int gy = by0 - 2 + r, gx = bx0 - 2 + cxx;
        float v = 0.f;
        if ((unsigned)gy < 2048u && (unsigned)gx < 2048u) v = x[(gy<<11)+gx];
        sX[r*37 + cxx] = v;
    }
    __syncthreads();

    float d[128];
    #pragma unroll
    for (int i = 0; i < 128; i++) d[i] = 0.f;

    const unsigned long long* w1u = (const unsigned long long*)sW1;

    for (int g = 0; g < 4; g++){
        if (g) __syncthreads();
        // conv1 (exact fp32) for ics g*8..g*8+7 over 34x34, write tf32 hi/lo planes
        for (int i = tid; i < 1156; i += 256){
            int fy = i/34, fx = i - fy*34;
            const float* base = sX + fy*37 + fx;
            unsigned long long vp[9];
            #pragma unroll
            for (int r = 0; r < 3; r++)
                #pragma unroll
                for (int c = 0; c < 3; c++) vp[r*3+c] = pack2(base[r*37+c]);
            int ao = i*ICP;
            #pragma unroll
            for (int q = 0; q < 4; q++){
                unsigned long long a = 0ull;
                #pragma unroll
                for (int t = 0; t < 9; t++) fma2(a, vp[t], w1u[t*16 + g*4 + q]);
                float2 f = unpack2(a);
                float v0 = fmaxf(f.x, 0.f), v1 = fmaxf(f.y, 0.f);
                unsigned h0 = f2tf(v0), h1 = f2tf(v1);
                float l0 = v0 - __uint_as_float(h0), l1 = v1 - __uint_as_float(h1);
                *(float2*)(sAhi + ao + 2*q) = make_float2(__uint_as_float(h0), __uint_as_float(h1));
                *(float2*)(sAlo + ao + 2*q) = make_float2(__uint_as_float(f2tf(l0)), __uint_as_float(f2tf(l1)));
            }
        }
        __syncthreads();

        for (int t = 0; t < 9; t++){
            int dy = t/3, dx = t - dy*3;            // 0..2 each
            // B fragments for this (t, g): 4 n-tiles x (hi,lo)
            unsigned bh[8], bl[8];
            #pragma unroll
            for (int nt = 0; nt < 4; nt++){
                int bi = (((t*4 + g)*4 + nt)*8 + lq)*4 + lc;
                float2 bv = sB[bi];
                bh[2*nt] = __float_as_uint(bv.x); bh[2*nt+1] = __float_as_uint(bv.y);
                float2 bw = sB[4608 + bi];
                bl[2*nt] = __float_as_uint(bw.x); bl[2*nt+1] = __float_as_uint(bw.y);
            }
            // A base offset: fy = 4*wid + (mt>>1) + dy ; fx = (mt&1)*16 + lq + dx  (halo origin -1)
            int base0 = ((4*wid + dy)*34 + lq + dx)*ICP + lc*2;
            #pragma unroll
            for (int mt = 0; mt < 8; mt++){
                int off = base0 + (mt>>1)*(34*ICP) + (mt&1)*(16*ICP);
                float2 ah0 = *(const float2*)(sAhi + off);
                float2 ah1 = *(const float2*)(sAhi + off + 8*ICP);
                float2 al0 = *(const float2*)(sAlo + off);
                float2 al1 = *(const float2*)(sAlo + off + 8*ICP);
                unsigned a0h = __float_as_uint(ah0.x), a1h = __float_as_uint(ah1.x);
                unsigned a2h = __float_as_uint(ah0.y), a3h = __float_as_uint(ah1.y);
                unsigned a0l = __float_as_uint(al0.x), a1l = __float_as_uint(al1.x);
                unsigned a2l = __float_as_uint(al0.y), a3l = __float_as_uint(al1.y);
                #pragma unroll
                for (int nt = 0; nt < 4; nt++){
                    float* dd = d + (mt*4 + nt)*4;
                    mma8(dd, a0h, a1h, a2h, a3h, bh[2*nt], bh[2*nt+1]);
                    mma8(dd, a0h, a1h, a2h, a3h, bl[2*nt], bl[2*nt+1]);
                    mma8(dd, a0l, a1l, a2l, a3l, bh[2*nt], bh[2*nt+1]);
                }
            }
        }
    }

    // epilogue: z = sum_oc relu(D)*w3 ; threshold -> labels
    #pragma unroll
    for (int mt = 0; mt < 8; mt++){
        float z0 = 0.f, z1 = 0.f;
        #pragma unroll
        for (int nt = 0; nt < 4; nt++){
            const float* dd = d + (mt*4 + nt)*4;
            float wl = sW3[nt*8 + 2*lc], wh = sW3[nt*8 + 2*lc + 1];
            z0 += fmaxf(dd[0], 0.f)*wl; z0 += fmaxf(dd[1], 0.f)*wh;
            z1 += fmaxf(dd[2], 0.f)*wl; z1 += fmaxf(dd[3], 0.f)*wh;
        }
        z0 += __shfl_xor_sync(0xffffffffu, z0, 1);
        z0 += __shfl_xor_sync(0xffffffffu, z0, 2);
        z1 += __shfl_xor_sync(0xffffffffu, z1, 1);
        z1 += __shfl_xor_sync(0xffffffffu, z1, 2);
        if (lc == 0){
            int y  = by0 + 4*wid + (mt>>1);
            int x0 = bx0 + (mt&1)*16 + lq;
            int p0 = (y<<11) + x0;
            int p1 = p0 + 8;
            g_labA[p0] = (z0 > 0.f) ? p0 : BIGL;
            g_labA[p1] = (z1 > 0.f) ? p1 : BIGL;
        }
    }
}

// ================= connected components (R7: early-exit, int4, sentinel ring) =================
#define CC_STRIDE 88
#define CC_CELLS  (82*CC_STRIDE)
#define CC_SMEM   (2*CC_CELLS*4)

__device__ __forceinline__ int cc_step(const int* __restrict__ cur, int* __restrict__ nxt, int off){
    int4 c = *(const int4*)(cur + off);
    int4 u = *(const int4*)(cur + off - CC_STRIDE);
    int4 d = *(const int4*)(cur + off + CC_STRIDE);
    int l = cur[off-1], r = cur[off+4];
    int4 o; int m;
    m = min(min(u.x,d.x), min(l,   c.y)); o.x = (c.x==BIGL) ? BIGL : min(c.x, m);
    m = min(min(u.y,d.y), min(c.x, c.z)); o.y = (c.y==BIGL) ? BIGL : min(c.y, m);
    m = min(min(u.z,d.z), min(c.y, c.w)); o.z = (c.z==BIGL) ? BIGL : min(c.z, m);
    m = min(min(u.w,d.w), min(c.z, r  )); o.w = (c.w==BIGL) ? BIGL : min(c.w, m);
    *(int4*)(nxt + off) = o;
    return (o.x^c.x) | (o.y^c.y) | (o.z^c.z) | (o.w^c.w);
}

__global__ __launch_bounds__(1024) void k_cc(const int* __restrict__ src, int* __restrict__ dst){
    extern __shared__ int sh[];
    int* A = sh;
    int* B = sh + CC_CELLS;
    int tid = threadIdx.x;
    int gx0 = blockIdx.x*64 - 8, gy0 = blockIdx.y*64 - 8;
    for (int s = tid; s < CC_CELLS; s += 1024){ A[s] = BIGL; B[s] = BIGL; }
    __syncthreads();
    for (int v = tid; v < 1600; v += 1024){
        int vy = v/20, vx = (v%20)*4;
        int gy = gy0 + vy, gxb = gx0 + vx;
        int off = (1+vy)*CC_STRIDE + 4 + vx;
        if ((unsigned)gy < 2048u && gxb >= 0 && gxb + 3 < 2048){
            *(int4*)(A + off) = *(const int4*)(src + (gy<<11) + gxb);
        } else if ((unsigned)gy < 2048u){
            #pragma unroll
            for (int k = 0; k < 4; k++){
                int gx = gxb + k;
                A[off+k] = ((unsigned)gx < 2048u) ? src[(gy<<11)+gx] : BIGL;
            }
        }
    }
    __syncthreads();
    int j0 = tid;
    int vy0 = j0/20, cx0 = (j0 - vy0*20)*4;
    int off0 = (1 + vy0)*CC_STRIDE + 4 + cx0;
    int j1 = tid + 1024;
    int vy1 = j1/20, cx1 = (j1 - vy1*20)*4;
    int off1 = (1 + vy1)*CC_STRIDE + 4 + cx1;
    bool has1 = (j1 < 1600);
    int* cur = A; int* nxt = B;
    for (int s = 1; s <= 8; s++){
        int changed = 0;
        if (vy0 >= s && vy0 <= 79-s && cx0+3 >= s && cx0 <= 79-s) changed |= cc_step(cur, nxt, off0);
        if (has1 && vy1 >= s && vy1 <= 79-s && cx1+3 >= s && cx1 <= 79-s) changed |= cc_step(cur, nxt, off1);
        if (!__syncthreads_or(changed)) break;
        int* t = cur; cur = nxt; nxt = t;
    }
    int row = tid >> 4, c16 = tid & 15;
    int soff = (9 + row)*CC_STRIDE + 12 + c16*4;
    int gy = blockIdx.y*64 + row, gx = blockIdx.x*64 + c16*4;
    *(int4*)(dst + (gy<<11) + gx) = *(const int4*)(cur + soff);
}

// ---------------- histogram ----------------
__global__ void k_zero_counts(){
    int i = blockIdx.x*1024 + threadIdx.x;
    if (i < NLBL) g_counts[i] = 0;
}
__global__ void k_count(){
    int p4 = (blockIdx.x*256 + threadIdx.x)*4;
    int4 l = *(const int4*)(g_labA + p4);
    #pragma unroll
    for (int k = 0; k < 4; k++){
        int lab = (k==0) ? l.x : (k==1) ? l.y : (k==2) ? l.z : l.w;
        unsigned mk = __match_any_sync(0xffffffffu, lab);
        int leader = __ffs(mk) - 1;
        if ((threadIdx.x & 31) == leader && lab != BIGL)
            atomicAdd(&g_counts[lab], __popc(mk));
    }
}

// ---------------- exact top-16 (count desc, label asc): two-stage ----------------
__global__ void k_topA(){
    __shared__ unsigned long long s[256*16];
    int chunk = (NLBL + NBLK_TOP - 1)/NBLK_TOP;
    int lo = blockIdx.x*chunk;
    int hi = min(NLBL, lo + chunk);
    unsigned long long best[16];
    #pragma unroll
    for (int i = 0; i < 16; i++) best[i] = 0ull;
    unsigned long long bmin = 0ull; int bpos = 0;
    for (int i = lo + threadIdx.x; i < hi; i += 256){
        unsigned long long key = ((unsigned long long)(unsigned)g_counts[i] << 32)
                               | (unsigned)(~(unsigned)i);
        if (key > bmin){
            best[bpos] = key;
            bmin = best[0]; bpos = 0;
            #pragma unroll
            for (int j = 1; j < 16; j++) if (best[j] < bmin){ bmin = best[j]; bpos = j; }
        }
    }
    for (int j = 0; j < 16; j++) s[threadIdx.x*16 + j] = best[j];
    __syncthreads();
    if (threadIdx.x < 32){
        for (int r = 0; r < 16; r++){
            unsigned long long m = 0ull; int mp = -1;
            for (int i = threadIdx.x; i < 4096; i += 32){
                unsigned long long v = s[i];
                if (v > m){ m = v; mp = i; }
            }
            for (int off = 16; off; off >>= 1){
                unsigned long long om = __shfl_down_sync(0xffffffffu, m, off);
                int op = __shfl_down_sync(0xffffffffu, mp, off);
                if (om > m){ m = om; mp = op; }
            }
            m  = __shfl_sync(0xffffffffu, m, 0);
            mp = __shfl_sync(0xffffffffu, mp, 0);
            if (threadIdx.x == 0){
                g_cand[blockIdx.x*16 + r] = m;
                if (mp >= 0) s[mp] = 0ull;
            }
            __syncwarp();
        }
    }
}
__global__ void k_topB(){
    __shared__ unsigned long long s[2048];
    int tid = threadIdx.x;
    for (int i = tid; i < 2048; i += 256) s[i] = (i < NBLK_TOP*16) ? g_cand[i] : 0ull;
    __syncthreads();
    if (tid < 32){
        for (int r = 0; r < 16; r++){
            unsigned long long m = 0ull; int mp = -1;
            for (int i = tid; i < 2048; i += 32){
                unsigned long long v = s[i];
                if (v > m){ m = v; mp = i; }
            }
            for (int off = 16; off; off >>= 1){
                unsigned long long om = __shfl_down_sync(0xffffffffu, m, off);
                int op = __shfl_down_sync(0xffffffffu, mp, off);
                if (om > m){ m = om; mp = op; }
            }
            m  = __shfl_sync(0xffffffffu, m, 0);
            mp = __shfl_sync(0xffffffffu, mp, 0);
            if (tid == 0){
                g_cnts[r] = (int)(m >> 32);
                g_lids[r] = (int)(~(unsigned)(m & 0xffffffffull));
                if (mp >= 0) s[mp] = 0ull;
            }
            __syncwarp();
        }
    }
}

// ---------------- bounding boxes ----------------
__global__ void k_bbinit(){
    int k = threadIdx.x;
    if (k < 16){ g_bbox[k][0] = 0x7FFFFFFF; g_bbox[k][1] = -1; g_bbox[k][2] = 0x7FFFFFFF; g_bbox[k][3] = -1; }
}
__global__ void k_bbox(){
    __shared__ int slid[16];
    __shared__ int sbb[16][4];
    int tid = threadIdx.x;
    if (tid < 16){
        slid[tid] = g_lids[tid];
        sbb[tid][0] = 0x7FFFFFFF; sbb[tid][1] = -1; sbb[tid][2] = 0x7FFFFFFF; sbb[tid][3] = -1;
    }
    __syncthreads();
    int base = blockIdx.x*1024;
    for (int q = 0; q < 4; q++){
        int p = base + q*256 + tid;
        int l = g_labA[p];
        if (l != BIGL){
            int y = p >> 11, x = p & 2047;
            #pragma unroll
            for (int k = 0; k < 16; k++) if (l == slid[k]){
                if (y < sbb[k][0]) atomicMin(&sbb[k][0], y);
                if (y > sbb[k][1]) atomicMax(&sbb[k][1], y);
                if (x < sbb[k][2]) atomicMin(&sbb[k][2], x);
                if (x > sbb[k][3]) atomicMax(&sbb[k][3], x);
            }
        }
    }
    __syncthreads();
    if (tid < 16 && sbb[tid][0] != 0x7FFFFFFF){
        atomicMin(&g_bbox[tid][0], sbb[tid][0]);
        atomicMax(&g_bbox[tid][1], sbb[tid][1]);
        atomicMin(&g_bbox[tid][2], sbb[tid][2]);
        atomicMax(&g_bbox[tid][3], sbb[tid][3]);
    }
}

// ---------------- ROI bilinear resize (227x227) ----------------
__global__ void k_roi(const float* __restrict__ img){
    int k = blockIdx.x;
    int y0 = g_bbox[k][0], y1 = g_bbox[k][1], x0 = g_bbox[k][2], x1 = g_bbox[k][3];
    if (y0 == 0x7FFFFFFF){ y0 = 0; y1 = 2047; x0 = 0; x1 = 2047; }
    float dy = (float)(y1 - y0), dx = (float)(x1 - x0);
    for (int idx = threadIdx.x; idx < 227*227; idx += blockDim.x){
        int i = idx/227, j = idx%227;
        float gy = (float)y0 + ((float)i/226.0f)*dy;
        float gx = (float)x0 + ((float)j/226.0f)*dx;
        int yf = min(max((int)floorf(gy), 0), 2046);
        int xf = min(max((int)floorf(gx), 0), 2046);
        float fy = gy - (float)yf, fx = gx - (float)xf;
        const float* r0 = img + (yf<<11) + xf;
        float v00 = r0[0], v01 = r0[1], v10 = r0[2048], v11 = r0[2049];
        g_roi[k*51529 + idx] = (1.f-fy)*((1.f-fx)*v00 + fx*v01) + fy*((1.f-fx)*v10 + fx*v11);
    }
}

// ---------------- classifier conv1: 7x7 s4 VALID, 1->16, relu ----------------
__global__ void k_c1(const float* __restrict__ cw1){
    __shared__ float sw[784];
    int tid = threadIdx.x;
    for (int i = tid; i < 784; i += 256) sw[i] = cw1[i];
    __syncthreads();
    int o = blockIdx.x*256 + tid;
    int k = o/50176, r = o%50176, oc = r/3136, s = r%3136, oy = s/56, ox = s%56;
    const float* roi = g_roi + k*51529;
    const float* wb = sw + oc*49;
    float a = 0.f;
    #pragma unroll
    for (int ky = 0; ky < 7; ky++){
        const float* rr = roi + (oy*4+ky)*227 + ox*4;
        #pragma unroll
        for (int kx = 0; kx < 7; kx++) a += rr[kx]*wb[ky*7+kx];
    }
    g_h1[o] = fmaxf(a, 0.f);
}

// ---------------- classifier conv2: 3x3 s2 VALID, 16->32, relu ----------------
__global__ void k_c2(const float* __restrict__ cw2){
    __shared__ float sw[4608];
    int tid = threadIdx.x;
    for (int i = tid; i < 4608; i += 256) sw[i] = cw2[i];
    __syncthreads();
    int o = blockIdx.x*256 + tid;
    int k = o/23328, r = o%23328, oc = r/729, s = r%729, oy = s/27, ox = s%27;
    const float* h = g_h1 + (size_t)k*16*3136;
    float a = 0.f;
    for (int ic = 0; ic < 16; ic++){
        const float* hb = h + ic*3136 + (oy*2)*56 + ox*2;
        const float* wb = sw + (oc*16+ic)*9;
        #pragma unroll
        for (int ky = 0; ky < 3; ky++)
            #pragma unroll
            for (int kx = 0; kx < 3; kx++)
                a += hb[ky*56+kx]*wb[ky*3+kx];
    }
    g_h2[o] = fmaxf(a, 0.f);
}

// ---------------- global mean + fc + argmax ----------------
__global__ void k_cls(const float* __restrict__ fc){
    __shared__ float ssum[32];
    int k = blockIdx.x;
    int tid = threadIdx.x, w = tid >> 5, lane = tid & 31;
    for (int oc = w*4; oc < w*4+4; oc++){
        float s = 0.f;
        const float* h = g_h2 + ((size_t)(k*32+oc))*729;
        for (int i = lane; i < 729; i += 32) s += h[i];
        for (int off = 16; off; off >>= 1) s += __shfl_down_sync(0xffffffffu, s, off);
        if (lane == 0) ssum[oc] = s;
    }
    __syncthreads();
    if (tid == 0){
        float best = -1e30f; int bc = 0;
        for (int c = 0; c < 4; c++){
            float lg = 0.f;
            for (int oc = 0; oc < 32; oc++) lg += (ssum[oc]*(1.0f/729.0f))*fc[oc*4+c];
            if (lg > best){ best = lg; bc = c; }
        }
        g_cls[k] = bc;
    }
}

// ---------------- final mask composition (vectorized) ----------------
__global__ void k_final(float* __restrict__ out){
    __shared__ int slid[16], scls[16];
    int tid = threadIdx.x;
    if (tid < 16){
        slid[tid] = (g_cnts[tid] >= MINSZ) ? g_lids[tid] : -1;
        scls[tid] = g_cls[tid];
    }
    __syncthreads();
    int p4 = (blockIdx.x*256 + tid)*4;
    int4 l = *(const int4*)(g_labA + p4);
    int c0 = -1, c1 = -1, c2 = -1, c3 = -1;
    #pragma unroll
    for (int k = 0; k < 16; k++){
        int lid = slid[k], cc = scls[k];
        if (l.x == lid) c0 = cc;
        if (l.y == lid) c1 = cc;
        if (l.z == lid) c2 = cc;
        if (l.w == lid) c3 = cc;
    }
    #pragma unroll
    for (int ch = 0; ch < 4; ch++){
        float4 o;
        o.x = (c0 == ch) ? 1.f : 0.f;
        o.y = (c1 == ch) ? 1.f : 0.f;
        o.z = (c2 == ch) ? 1.f : 0.f;
        o.w = (c3 == ch) ? 1.f : 0.f;
        *(float4*)(out + (size_t)ch*NPIX + p4) = o;
    }
}

// ---------------- launch ----------------
extern "C" void kernel_launch(void* const* d_in, const int* in_sizes, int n_in,
                              void* d_out, int out_size){
    const float *x = nullptr, *w1 = nullptr, *w2 = nullptr, *w3 = nullptr;
    const float *cw1 = nullptr, *cw2 = nullptr, *fc = nullptr;
    for (int i = 0; i < n_in; i++){
        switch (in_sizes[i]){
            case 4194304: x   = (const float*)d_in[i]; break;
            case 288:     w1  = (const float*)d_in[i]; break;
            case 9216:    w2  = (const float*)d_in[i]; break;
            case 32:      w3  = (const float*)d_in[i]; break;
            case 784:     cw1 = (const float*)d_in[i]; break;
            case 4608:    cw2 = (const float*)d_in[i]; break;
            case 128:     fc  = (const float*)d_in[i]; break;
            default: break;
        }
    }
    float* out = (float*)d_out;

    cudaFuncSetAttribute(k_conv_tc, cudaFuncAttributeMaxDynamicSharedMemorySize, CONV_SMEM);
    cudaFuncSetAttribute(k_cc, cudaFuncAttributeMaxDynamicSharedMemorySize, CC_SMEM);

    k_conv_tc<<<dim3(64,64), 256, CONV_SMEM>>>(x, w1, w2, w3);

    int* la = nullptr; int* lb = nullptr;
    cudaGetSymbolAddress((void**)&la, g_labA);
    cudaGetSymbolAddress((void**)&lb, g_labB);
    for (int i = 0; i < 4; i++){
        k_cc<<<dim3(32,32), 1024, CC_SMEM>>>(la, lb);
        k_cc<<<dim3(32,32), 1024, CC_SMEM>>>(lb, la);
    }

    k_zero_counts<<<(NLBL+1023)/1024, 1024>>>();
    k_count<<<NPIX/1024, 256>>>();
    k_topA<<<NBLK_TOP, 256>>>();
    k_topB<<<1, 256>>>();

    k_bbinit<<<1, 16>>>();
    k_bbox<<<NPIX/1024, 256>>>();

    k_roi<<<16, 256>>>(x);
    k_c1<<<802816/256, 256>>>(cw1);
    k_c2<<<373248/256, 256>>>(cw2);
    k_cls<<<16, 256>>>(fc);

    k_final<<<NPIX/1024, 256>>>(out);
}